// round 6
// baseline (speedup 1.0000x reference)
#include <cuda_runtime.h>
#include <cuda_bf16.h>
#include <cstdint>

// Problem constants
#define BB 16
#define SS 1024
#define DD 1024
#define HH 16
#define HD 64
#define K3 3072   // gemm split-K: [hi|hi|lo] x [hi|lo|hi]

// Scratch (static __device__ arrays -- no allocations)
__device__ __nv_bfloat16 g_xs[BB * SS * K3];        // ~100 MB
__device__ __nv_bfloat16 g_ws[2048 * K3];           // 12 MB
// Split Q/K, head-major: [(b*16+h)*1024 + s][128] = [qhi(64) | qlo(64)]
__device__ __nv_bfloat16 g_qs[BB * HH * SS * 128];  // 64 MB
__device__ __nv_bfloat16 g_ks[BB * HH * SS * 128];  // 64 MB
// V transposed split: [(bh*2 + hl)*64 + dim][1024 keys]
__device__ __nv_bfloat16 g_vt[BB * HH * 2 * 64 * SS]; // 64 MB

// ---------------------------------------------------------------------------
// PTX helpers (sm_80-level PTX; valid on compute_103)
// ---------------------------------------------------------------------------
__device__ __forceinline__ uint32_t smem_u32(const void* p) {
    uint32_t a;
    asm("{ .reg .u64 t; cvta.to.shared.u64 t, %1; cvt.u32.u64 %0, t; }"
        : "=r"(a) : "l"(p));
    return a;
}
__device__ __forceinline__ void cp16(uint32_t saddr, const void* g) {
    asm volatile("cp.async.cg.shared.global [%0], [%1], 16;" :: "r"(saddr), "l"(g));
}
__device__ __forceinline__ void ldsm_x4(uint32_t& r0, uint32_t& r1, uint32_t& r2,
                                        uint32_t& r3, uint32_t addr) {
    asm volatile("ldmatrix.sync.aligned.m8n8.x4.shared.b16 {%0,%1,%2,%3}, [%4];"
                 : "=r"(r0), "=r"(r1), "=r"(r2), "=r"(r3) : "r"(addr));
}
__device__ __forceinline__ void mma_bf16(float* c, uint32_t a0, uint32_t a1,
                                         uint32_t a2, uint32_t a3,
                                         uint32_t b0, uint32_t b1) {
    asm volatile(
        "mma.sync.aligned.m16n8k16.row.col.f32.bf16.bf16.f32 "
        "{%0,%1,%2,%3}, {%4,%5,%6,%7}, {%8,%9}, {%0,%1,%2,%3};"
        : "+f"(c[0]), "+f"(c[1]), "+f"(c[2]), "+f"(c[3])
        : "r"(a0), "r"(a1), "r"(a2), "r"(a3), "r"(b0), "r"(b1));
}
__device__ __forceinline__ uint32_t sw128(uint32_t byte) {
    return byte ^ ((byte >> 3) & 0x70);
}
__device__ __forceinline__ float ex2f(float x) {
    float y;
    asm("ex2.approx.ftz.f32 %0, %1;" : "=f"(y) : "f"(x));
    return y;
}
__device__ __forceinline__ uint32_t pack_bf2(float a, float b) {
    __nv_bfloat162 h;
    h.x = __float2bfloat16(a);
    h.y = __float2bfloat16(b);
    return *reinterpret_cast<uint32_t*>(&h);
}

// ---------------------------------------------------------------------------
// bf16 split conversion for the projection GEMM
// ---------------------------------------------------------------------------
__global__ void conv_x(const float* __restrict__ X) {
    int i = blockIdx.x * blockDim.x + threadIdx.x;
    if (i >= BB * SS * DD) return;
    int r = i >> 10, c = i & 1023;
    float x = X[i];
    __nv_bfloat16 hi = __float2bfloat16(x);
    __nv_bfloat16 lo = __float2bfloat16(x - __bfloat162float(hi));
    size_t base = (size_t)r * K3;
    g_xs[base + c] = hi;
    g_xs[base + 1024 + c] = hi;
    g_xs[base + 2048 + c] = lo;
}
__global__ void conv_w(const float* __restrict__ W) {
    int i = blockIdx.x * blockDim.x + threadIdx.x;
    if (i >= 2048 * 1024) return;
    int r = i >> 10, c = i & 1023;
    float w = W[i];
    __nv_bfloat16 hi = __float2bfloat16(w);
    __nv_bfloat16 lo = __float2bfloat16(w - __bfloat162float(hi));
    size_t base = (size_t)r * K3;
    g_ws[base + c] = hi;
    g_ws[base + 1024 + c] = lo;
    g_ws[base + 2048 + c] = hi;
}

// V transpose + split: per (kb, h, b) tile of 64 keys x 64 dims
__global__ __launch_bounds__(256) void conv_vt(const float* __restrict__ X) {
    __shared__ float tile[64][65];
    int kb = blockIdx.x, h = blockIdx.y, b = blockIdx.z;
    int tid = threadIdx.x;
#pragma unroll
    for (int i = 0; i < 4; i++) {
        int row = i * 16 + tid / 16;
        int c4 = (tid % 16) * 4;
        float4 v = *(const float4*)&X[((size_t)b * SS + kb * 64 + row) * DD + h * 64 + c4];
        tile[row][c4 + 0] = v.x;
        tile[row][c4 + 1] = v.y;
        tile[row][c4 + 2] = v.z;
        tile[row][c4 + 3] = v.w;
    }
    __syncthreads();
    int bh = b * HH + h;
#pragma unroll
    for (int i = 0; i < 16; i++) {
        int e = tid + i * 256;
        int dim = e >> 6, key = e & 63;
        float x = tile[key][dim];
        __nv_bfloat16 hi = __float2bfloat16(x);
        __nv_bfloat16 lo = __float2bfloat16(x - __bfloat162float(hi));
        g_vt[((size_t)(bh * 2 + 0) * 64 + dim) * SS + kb * 64 + key] = hi;
        g_vt[((size_t)(bh * 2 + 1) * 64 + dim) * SS + kb * 64 + key] = lo;
    }
}

// ---------------------------------------------------------------------------
// HMMA bf16 GEMM: C[16384, 2048] = Xs @ Ws^T (K'=3072) + bias
// CTA tile 128x256, BK=64, 3-stage cp.async, 8 warps (2x4), warp tile 64x64.
// Epilogue emits split bf16 directly to g_qs / g_ks (q pre-scaled by
// 0.125*log2(e) so attention softmax can use exp2).
// ---------------------------------------------------------------------------
#define BK 64
#define NSTAGE 3
#define STAGE_BYTES 49152              // A 16KB + B 32KB
#define GEMM_SMEM (NSTAGE * STAGE_BYTES)

__global__ __launch_bounds__(256, 1) void gemm_hmma(const float* __restrict__ bias) {
    extern __shared__ char smem[];
    const uint32_t sbase = smem_u32(smem);
    const int tid = threadIdx.x;
    const int lane = tid & 31;
    const int wid = tid >> 5;
    const int warp_m = wid >> 2;        // 0..1  (x64 rows)
    const int warp_n = wid & 3;         // 0..3  (x64 cols)
    const int n0 = blockIdx.x * 256;
    const int m0 = blockIdx.y * 128;

    const __nv_bfloat16* gA = g_xs + (size_t)m0 * K3;
    const __nv_bfloat16* gB = g_ws + (size_t)n0 * K3;

    // Per-stage loader: A 128 rows x 128B, B 256 rows x 128B, SW128.
    auto load_stage = [&](int kc, int s) {
        uint32_t sA = sbase + s * STAGE_BYTES;
        uint32_t sB = sA + 16384;
        const __nv_bfloat16* a = gA + kc * BK;
        const __nv_bfloat16* b = gB + kc * BK;
#pragma unroll
        for (int i = 0; i < 4; i++) {
            int idx = tid + i * 256;            // 0..1023
            int r = idx >> 3, q = idx & 7;
            uint32_t sw = sw128(r * 128 + q * 16);
            cp16(sA + sw, a + (size_t)r * K3 + q * 8);
        }
#pragma unroll
        for (int i = 0; i < 8; i++) {           // 2048 x 16B
            int idx = tid + i * 256;
            int r = idx >> 3, q = idx & 7;
            uint32_t sw = sw128(r * 128 + q * 16);
            cp16(sB + sw, b + (size_t)r * K3 + q * 8);
        }
        asm volatile("cp.async.commit_group;" ::: "memory");
    };

    float acc[4][8][4];
#pragma unroll
    for (int mi = 0; mi < 4; mi++)
#pragma unroll
        for (int nt = 0; nt < 8; nt++)
#pragma unroll
            for (int k = 0; k < 4; k++) acc[mi][nt][k] = 0.0f;

    const int NK = K3 / BK;  // 48
    load_stage(0, 0);
    load_stage(1, 1);

    for (int kc = 0; kc < NK; kc++) {
        int s = kc % NSTAGE;
        if (kc + 1 < NK) asm volatile("cp.async.wait_group 1;" ::: "memory");
        else             asm volatile("cp.async.wait_group 0;" ::: "memory");
        __syncthreads();
        if (kc + 2 < NK) load_stage(kc + 2, (kc + 2) % NSTAGE);

        uint32_t sA = sbase + s * STAGE_BYTES;
        uint32_t sB = sA + 16384;

#pragma unroll
        for (int kk = 0; kk < BK / 16; kk++) {   // 4 k-steps of 16
            int colb = kk * 32 + ((lane >> 4) << 4);
            uint32_t a[4][4];
#pragma unroll
            for (int mi = 0; mi < 4; mi++) {
                int row = warp_m * 64 + mi * 16 + (lane & 15);
                ldsm_x4(a[mi][0], a[mi][1], a[mi][2], a[mi][3],
                        sA + sw128(row * 128 + colb));
            }
#pragma unroll
            for (int p = 0; p < 4; p++) {
                uint32_t b0, b1, b2, b3;
                int row = warp_n * 64 + p * 16 + (lane & 15);
                ldsm_x4(b0, b1, b2, b3, sB + sw128(row * 128 + colb));
#pragma unroll
                for (int mi = 0; mi < 4; mi++) {
                    mma_bf16(acc[mi][p * 2 + 0], a[mi][0], a[mi][1], a[mi][2],
                             a[mi][3], b0, b2);
                    mma_bf16(acc[mi][p * 2 + 1], a[mi][0], a[mi][1], a[mi][2],
                             a[mi][3], b1, b3);
                }
            }
        }
        __syncthreads();
    }

    // Epilogue: bias, scale (q only), bf16 split, head-major store
    const float QSCALE = 0.18033688011112042f;  // 0.125 * log2(e)
    float scale = (n0 < 1024) ? QSCALE : 1.0f;
    __nv_bfloat16* dst = (n0 < 1024) ? g_qs : g_ks;

#pragma unroll
    for (int mi = 0; mi < 4; mi++) {
#pragma unroll
        for (int nt = 0; nt < 8; nt++) {
            int c = warp_n * 64 + nt * 8 + (lane & 3) * 2;
            int nn = (n0 + c) & 1023;
            int hh_ = nn >> 6, d = nn & 63;
            float b0 = __ldg(&bias[n0 + c]);
            float b1 = __ldg(&bias[n0 + c + 1]);
#pragma unroll
            for (int rr = 0; rr < 2; rr++) {
                int r = m0 + warp_m * 64 + mi * 16 + (lane >> 2) + rr * 8;
                int bb = r >> 10, s2 = r & 1023;
                size_t base = ((size_t)(bb * HH + hh_) * SS + s2) * 128;
                float v0 = (acc[mi][nt][rr * 2 + 0] + b0) * scale;
                float v1 = (acc[mi][nt][rr * 2 + 1] + b1) * scale;
                __nv_bfloat16 h0 = __float2bfloat16(v0);
                __nv_bfloat16 h1 = __float2bfloat16(v1);
                __nv_bfloat162 hh, ll;
                hh.x = h0; hh.y = h1;
                ll.x = __float2bfloat16(v0 - __bfloat162float(h0));
                ll.y = __float2bfloat16(v1 - __bfloat162float(h1));
                *(__nv_bfloat162*)&dst[base + d] = hh;
                *(__nv_bfloat162*)&dst[base + 64 + d] = ll;
            }
        }
    }
}

// ---------------------------------------------------------------------------
// HMMA flash attention. CTA = (qb: 128 rows, h, b). 8 warps x 16 q-rows.
// BN=64 keys/iter, 2-stage cp.async. 3-term split on both QK and PV.
// (unchanged from round-5 passing kernel)
// ---------------------------------------------------------------------------
#define ATT_SMEM (32768 + 2 * 32768)  // Q tiles + 2 stages = 96 KB

__global__ __launch_bounds__(256) void attn_tc(float* __restrict__ Out) {
    extern __shared__ char smem[];
    const uint32_t sb = smem_u32(smem);
    const int tid = threadIdx.x;
    const int lane = tid & 31;
    const int wid = tid >> 5;
    const int qb = blockIdx.x, h = blockIdx.y, b = blockIdx.z;
    const int bh = b * HH + h;

    const uint32_t QHI = sb, QLO = sb + 16384;
    auto STAGE = [&](int s) { return sb + 32768 + s * 32768; };

    {
        const __nv_bfloat16* qsrc = g_qs + ((size_t)bh * SS + qb * 128) * 128;
#pragma unroll
        for (int i = 0; i < 4; i++) {
            int e = tid + i * 256;
            int row = e >> 3, q = e & 7;
            uint32_t sw = sw128(row * 128 + q * 16);
            cp16(QHI + sw, qsrc + (size_t)row * 128 + q * 8);
            cp16(QLO + sw, qsrc + (size_t)row * 128 + 64 + q * 8);
        }
        asm volatile("cp.async.commit_group;" ::: "memory");
    }

    auto load_kv = [&](int kb, int s) {
        uint32_t st = STAGE(s);
        const __nv_bfloat16* ks = g_ks + ((size_t)bh * SS + kb * 64) * 128;
        const __nv_bfloat16* vh = g_vt + (size_t)(bh * 2 + 0) * 64 * SS + kb * 64;
        const __nv_bfloat16* vl = g_vt + (size_t)(bh * 2 + 1) * 64 * SS + kb * 64;
#pragma unroll
        for (int i = 0; i < 2; i++) {
            int e = tid + i * 256;
            int row = e >> 3, q = e & 7;
            uint32_t sw = sw128(row * 128 + q * 16);
            cp16(st + sw, ks + (size_t)row * 128 + q * 8);
            cp16(st + 8192 + sw, ks + (size_t)row * 128 + 64 + q * 8);
            cp16(st + 16384 + sw, vh + (size_t)row * SS + q * 8);
            cp16(st + 24576 + sw, vl + (size_t)row * SS + q * 8);
        }
        asm volatile("cp.async.commit_group;" ::: "memory");
    };

    load_kv(0, 0);
    load_kv(1, 1);

    float oacc[8][4];
#pragma unroll
    for (int t = 0; t < 8; t++)
#pragma unroll
        for (int k = 0; k < 4; k++) oacc[t][k] = 0.0f;
    float m0 = -1e30f, m1 = -1e30f, l0 = 0.0f, l1 = 0.0f;

    const int NIT = SS / 64;  // 16
    for (int kb = 0; kb < NIT; kb++) {
        int s = kb & 1;
        if (kb + 1 < NIT) asm volatile("cp.async.wait_group 1;" ::: "memory");
        else              asm volatile("cp.async.wait_group 0;" ::: "memory");
        __syncthreads();

        uint32_t st = STAGE(s);
        float sacc[8][4];
#pragma unroll
        for (int t = 0; t < 8; t++)
#pragma unroll
            for (int k = 0; k < 4; k++) sacc[t][k] = 0.0f;

#pragma unroll
        for (int pass = 0; pass < 3; pass++) {
            uint32_t aT = (pass == 2) ? QLO : QHI;
            uint32_t bT = (pass == 1) ? (st + 8192) : st;
#pragma unroll
            for (int kk = 0; kk < 4; kk++) {
                int colb = kk * 32 + ((lane >> 4) << 4);
                uint32_t a0, a1, a2, a3;
                {
                    int row = wid * 16 + (lane & 15);
                    ldsm_x4(a0, a1, a2, a3, aT + sw128(row * 128 + colb));
                }
#pragma unroll
                for (int p = 0; p < 4; p++) {
                    uint32_t r0, r1, r2, r3;
                    int row = p * 16 + (lane & 15);
                    ldsm_x4(r0, r1, r2, r3, bT + sw128(row * 128 + colb));
                    mma_bf16(sacc[2 * p + 0], a0, a1, a2, a3, r0, r2);
                    mma_bf16(sacc[2 * p + 1], a0, a1, a2, a3, r1, r3);
                }
            }
        }

        float mx0 = -1e30f, mx1 = -1e30f;
#pragma unroll
        for (int t = 0; t < 8; t++) {
            mx0 = fmaxf(mx0, fmaxf(sacc[t][0], sacc[t][1]));
            mx1 = fmaxf(mx1, fmaxf(sacc[t][2], sacc[t][3]));
        }
        mx0 = fmaxf(mx0, __shfl_xor_sync(0xffffffffu, mx0, 1));
        mx0 = fmaxf(mx0, __shfl_xor_sync(0xffffffffu, mx0, 2));
        mx1 = fmaxf(mx1, __shfl_xor_sync(0xffffffffu, mx1, 1));
        mx1 = fmaxf(mx1, __shfl_xor_sync(0xffffffffu, mx1, 2));
        float mn0 = fmaxf(m0, mx0), mn1 = fmaxf(m1, mx1);
        float c0 = ex2f(m0 - mn0), c1 = ex2f(m1 - mn1);
        m0 = mn0; m1 = mn1;

        uint32_t pa_hi[4][4], pa_lo[4][4];
        float sum0 = 0.0f, sum1 = 0.0f;
#pragma unroll
        for (int t = 0; t < 8; t++) {
            float p0 = ex2f(sacc[t][0] - mn0);
            float p1 = ex2f(sacc[t][1] - mn0);
            float p2 = ex2f(sacc[t][2] - mn1);
            float p3 = ex2f(sacc[t][3] - mn1);
            sum0 += p0 + p1;
            sum1 += p2 + p3;
            __nv_bfloat16 h0 = __float2bfloat16(p0), h1 = __float2bfloat16(p1);
            __nv_bfloat16 h2 = __float2bfloat16(p2), h3 = __float2bfloat16(p3);
            int kk = t >> 1, o = (t & 1) * 2;
            {
                __nv_bfloat162 u; u.x = h0; u.y = h1;
                pa_hi[kk][o + 0] = *reinterpret_cast<uint32_t*>(&u);
            }
            {
                __nv_bfloat162 u; u.x = h2; u.y = h3;
                pa_hi[kk][o + 1] = *reinterpret_cast<uint32_t*>(&u);
            }
            pa_lo[kk][o + 0] = pack_bf2(p0 - __bfloat162float(h0),
                                        p1 - __bfloat162float(h1));
            pa_lo[kk][o + 1] = pack_bf2(p2 - __bfloat162float(h2),
                                        p3 - __bfloat162float(h3));
        }
        sum0 += __shfl_xor_sync(0xffffffffu, sum0, 1);
        sum0 += __shfl_xor_sync(0xffffffffu, sum0, 2);
        sum1 += __shfl_xor_sync(0xffffffffu, sum1, 1);
        sum1 += __shfl_xor_sync(0xffffffffu, sum1, 2);
        l0 = l0 * c0 + sum0;
        l1 = l1 * c1 + sum1;
#pragma unroll
        for (int t = 0; t < 8; t++) {
            oacc[t][0] *= c0; oacc[t][1] *= c0;
            oacc[t][2] *= c1; oacc[t][3] *= c1;
        }

#pragma unroll
        for (int pass = 0; pass < 3; pass++) {
            uint32_t vT = (pass == 1) ? (st + 24576) : (st + 16384);
            const uint32_t (*pa)[4] = (pass == 2) ? pa_lo : pa_hi;
#pragma unroll
            for (int kk = 0; kk < 4; kk++) {
                int colb = kk * 32 + ((lane >> 4) << 4);
#pragma unroll
                for (int dt = 0; dt < 4; dt++) {
                    uint32_t r0, r1, r2, r3;
                    int row = dt * 16 + (lane & 15);
                    ldsm_x4(r0, r1, r2, r3, vT + sw128(row * 128 + colb));
                    mma_bf16(oacc[2 * dt + 0], pa[kk][0], pa[kk][1], pa[kk][2],
                             pa[kk][3], r0, r2);
                    mma_bf16(oacc[2 * dt + 1], pa[kk][0], pa[kk][1], pa[kk][2],
                             pa[kk][3], r1, r3);
                }
            }
        }

        __syncthreads();
        if (kb + 2 < NIT) load_kv(kb + 2, s);
    }

    float inv0 = 1.0f / l0, inv1 = 1.0f / l1;
    int r_g0 = qb * 128 + wid * 16 + (lane >> 2);
#pragma unroll
    for (int t = 0; t < 8; t++) {
        int col = h * 64 + t * 8 + (lane & 3) * 2;
        float2 v0 = make_float2(oacc[t][0] * inv0, oacc[t][1] * inv0);
        float2 v1 = make_float2(oacc[t][2] * inv1, oacc[t][3] * inv1);
        *(float2*)&Out[((size_t)b * SS + r_g0) * DD + col] = v0;
        *(float2*)&Out[((size_t)b * SS + r_g0 + 8) * DD + col] = v1;
    }
}

extern "C" void kernel_launch(void* const* d_in, const int* in_sizes, int n_in,
                              void* d_out, int out_size) {
    const float* X = (const float*)d_in[0];     // [16,1024,1024]
    const float* W = (const float*)d_in[1];     // [2048,1024]
    const float* bias = (const float*)d_in[2];  // [2048]
    float* Out = (float*)d_out;                 // [16,1024,1024]

    cudaFuncSetAttribute(gemm_hmma, cudaFuncAttributeMaxDynamicSharedMemorySize,
                         GEMM_SMEM);
    cudaFuncSetAttribute(attn_tc, cudaFuncAttributeMaxDynamicSharedMemorySize,
                         ATT_SMEM);

    conv_x<<<(BB * SS * DD + 255) / 256, 256>>>(X);
    conv_w<<<(2048 * 1024 + 255) / 256, 256>>>(W);
    conv_vt<<<dim3(16, HH, BB), 256>>>(X);
    gemm_hmma<<<dim3(8, 128), 256, GEMM_SMEM>>>(bias);

    attn_tc<<<dim3(SS / 128, HH, BB), 256, ATT_SMEM>>>(Out);
}